// round 17
// baseline (speedup 1.0000x reference)
#include <cuda_runtime.h>
#include <cuda_bf16.h>
#include <cstdint>

// MoELayer: B=2,S=2048,H=2048,I=4096,E=8, top-2
#define TT 4096
#define HH 2048
#define II 4096
#define EE 8
#define NASG (2*TT)

#define BM 128
#define BN 128
#define BK 32
#define AS 40    // A smem row stride (elems)
#define BS 136   // B smem row stride (elems)

// stage layout (bf16 elems): Ah 5120 | Al 5120 | B0h 4352 | B0l | B1h | B1l
#define S_AL  5120
#define S_B0H 10240
#define S_B0L 14592
#define S_B1H 18944
#define S_B1L 23296
#define STAGE 27648
#define SMEMB (STAGE * 2 * 2)   // 110592 B

// ---------------- static device scratch --------------------------------------
__device__ int   g_cnt[EE];
__device__ int   g_off[EE];
__device__ int   g_tok[EE * TT];
__device__ int   g_asg[TT * 2];
__device__ float g_wt[TT * 2];

__device__ __nv_bfloat16 g_xh[(size_t)TT * HH], g_xl[(size_t)TT * HH];
__device__ __nv_bfloat16 g_wgh[(size_t)EE * HH * II], g_wgl[(size_t)EE * HH * II];
__device__ __nv_bfloat16 g_wuh[(size_t)EE * HH * II], g_wul[(size_t)EE * HH * II];
__device__ __nv_bfloat16 g_wdh[(size_t)EE * II * HH], g_wdl[(size_t)EE * II * HH];
__device__ __nv_bfloat16 g_hh[(size_t)NASG * II], g_hl[(size_t)NASG * II];
__device__ float         g_y[(size_t)NASG * HH];

// ---------------- helpers ----------------------------------------------------
__device__ __forceinline__ void ldm4(uint32_t* r, const __nv_bfloat16* p) {
    uint32_t a = (uint32_t)__cvta_generic_to_shared(p);
    asm volatile("ldmatrix.sync.aligned.m8n8.x4.shared.b16 {%0,%1,%2,%3}, [%4];"
                 : "=r"(r[0]), "=r"(r[1]), "=r"(r[2]), "=r"(r[3]) : "r"(a));
}
__device__ __forceinline__ void ldm4t(uint32_t* r, const __nv_bfloat16* p) {
    uint32_t a = (uint32_t)__cvta_generic_to_shared(p);
    asm volatile("ldmatrix.sync.aligned.m8n8.x4.trans.shared.b16 {%0,%1,%2,%3}, [%4];"
                 : "=r"(r[0]), "=r"(r[1]), "=r"(r[2]), "=r"(r[3]) : "r"(a));
}
__device__ __forceinline__ void mma16816(float* c, const uint32_t* a, const uint32_t* b) {
    asm volatile("mma.sync.aligned.m16n8k16.row.col.f32.bf16.bf16.f32 "
                 "{%0,%1,%2,%3},{%4,%5,%6,%7},{%8,%9},{%0,%1,%2,%3};"
                 : "+f"(c[0]), "+f"(c[1]), "+f"(c[2]), "+f"(c[3])
                 : "r"(a[0]), "r"(a[1]), "r"(a[2]), "r"(a[3]), "r"(b[0]), "r"(b[1]));
}
__device__ __forceinline__ void cpa8(__nv_bfloat16* dst, const __nv_bfloat16* src, bool v) {
    uint32_t d = (uint32_t)__cvta_generic_to_shared(dst);
    int sz = v ? 8 : 0;
    asm volatile("cp.async.ca.shared.global [%0], [%1], 8, %2;\n"
                 :: "r"(d), "l"(src), "r"(sz));
}
__device__ __forceinline__ void split2(float v, __nv_bfloat16& h, __nv_bfloat16& l) {
    h = __float2bfloat16_rn(v);
    l = __float2bfloat16_rn(v - __bfloat162float(h));
}
__device__ __forceinline__ void splitpack(float4 v, uint2& H, uint2& L) {
    __nv_bfloat16 h0,h1,h2,h3,l0,l1,l2,l3;
    split2(v.x,h0,l0); split2(v.y,h1,l1); split2(v.z,h2,l2); split2(v.w,h3,l3);
    __nv_bfloat162 a, b;
    a.x = h0; a.y = h1; b.x = h2; b.y = h3;
    H.x = *(uint32_t*)&a; H.y = *(uint32_t*)&b;
    a.x = l0; a.y = l1; b.x = l2; b.y = l3;
    L.x = *(uint32_t*)&a; L.y = *(uint32_t*)&b;
}

// ---------------- small kernels ----------------------------------------------
__global__ void zero_cnt_kernel() { if (threadIdx.x < EE) g_cnt[threadIdx.x] = 0; }

__global__ void split_kernel(const float4* __restrict__ src,
                             uint2* __restrict__ hi, uint2* __restrict__ lo) {
    size_t i = (size_t)blockIdx.x * blockDim.x + threadIdx.x;
    uint2 H, L;
    splitpack(src[i], H, L);
    hi[i] = H; lo[i] = L;
}

__global__ void router_kernel(const float* __restrict__ x, const float* __restrict__ gw) {
    int t = blockIdx.x;
    const float* xr = x + (size_t)t * HH;
    __shared__ float slog[EE];
    int warp = threadIdx.x >> 5, lane = threadIdx.x & 31;
    float s = 0.f;
    for (int h = lane; h < HH; h += 32) s += xr[h] * gw[h * EE + warp];
    #pragma unroll
    for (int o = 16; o; o >>= 1) s += __shfl_xor_sync(0xffffffffu, s, o);
    if (lane == 0) slog[warp] = s;
    __syncthreads();
    if (threadIdx.x == 0) {
        float mx = slog[0];
        #pragma unroll
        for (int e = 1; e < EE; e++) mx = fmaxf(mx, slog[e]);
        float p[EE];
        #pragma unroll
        for (int e = 0; e < EE; e++) p[e] = __expf(slog[e] - mx);
        int i0 = 0;
        #pragma unroll
        for (int e = 1; e < EE; e++) if (p[e] > p[i0]) i0 = e;
        int i1 = (i0 == 0) ? 1 : 0;
        #pragma unroll
        for (int e = 0; e < EE; e++) if (e != i0 && p[e] > p[i1]) i1 = e;
        float w0 = p[i0], w1 = p[i1], ws = w0 + w1;
        w0 /= ws; w1 /= ws;
        int s0 = atomicAdd(&g_cnt[i0], 1);
        int s1 = atomicAdd(&g_cnt[i1], 1);
        g_tok[i0 * TT + s0] = t;
        g_tok[i1 * TT + s1] = t;
        g_asg[t * 2 + 0] = (i0 << 12) | s0;  g_wt[t * 2 + 0] = w0;
        g_asg[t * 2 + 1] = (i1 << 12) | s1;  g_wt[t * 2 + 1] = w1;
    }
}

__global__ void prefix_kernel() {
    if (threadIdx.x == 0) {
        int a = 0;
        #pragma unroll
        for (int e = 0; e < EE; e++) { g_off[e] = a; a += g_cnt[e]; }
    }
}

// ---------------- dual-N-tile pipelined split-bf16 GEMM ----------------------
// Computes two 128-wide output tiles per CTA from ONE staged A tile.
// FUSE=1 (gate+up): B0=gate planes, B1=up planes at SAME col -> swiglu -> hh/hl bf16.
// FUSE=0 (down): B0==B1=wd planes, cols bx*256 and bx*256+128 -> y fp32.
template <bool GATHER, bool FUSE>
__global__ __launch_bounds__(256) void gemm3(
    const __nv_bfloat16* __restrict__ Ahg, const __nv_bfloat16* __restrict__ Alg,
    const __nv_bfloat16* __restrict__ B0h, const __nv_bfloat16* __restrict__ B0l,
    const __nv_bfloat16* __restrict__ B1h, const __nv_bfloat16* __restrict__ B1l,
    float* __restrict__ C, int K, int N)
{
    int e = blockIdx.z;
    int Me = g_cnt[e];
    int m0 = blockIdx.y * BM;
    if (m0 >= Me) return;
    int offe = g_off[e];

    int col0 = blockIdx.x * (FUSE ? BN : 2 * BN);
    int col1off = FUSE ? 0 : BN;
    const __nv_bfloat16* B0hp = B0h + (size_t)e * K * N + col0;
    const __nv_bfloat16* B0lp = B0l + (size_t)e * K * N + col0;
    const __nv_bfloat16* B1hp = B1h + (size_t)e * K * N + col0 + col1off;
    const __nv_bfloat16* B1lp = B1l + (size_t)e * K * N + col0 + col1off;

    extern __shared__ __nv_bfloat16 sm[];

    int tid = threadIdx.x, lane = tid & 31, warp = tid >> 5;
    int wm = (warp & 1) * 64, wn = (warp >> 1) * 32;

    int aoff[4]; bool av[4];
    #pragma unroll
    for (int i = 0; i < 4; i++) {
        int id = tid + i * 256;
        int gm = m0 + (id >> 3);
        av[i] = gm < Me;
        int row = 0;
        if (av[i]) row = GATHER ? g_tok[e * TT + gm] : (offe + gm);
        aoff[i] = row * K;
    }

    float acc0[4][4][4], acc1[4][4][4];
    #pragma unroll
    for (int mt = 0; mt < 4; mt++)
        #pragma unroll
        for (int nt = 0; nt < 4; nt++)
            #pragma unroll
            for (int i = 0; i < 4; i++) { acc0[mt][nt][i] = 0.f; acc1[mt][nt][i] = 0.f; }

    auto issue = [&](int k0, int s) {
        __nv_bfloat16* base = sm + s * STAGE;
        #pragma unroll
        for (int i = 0; i < 4; i++) {
            int id = tid + i * 256;
            int r = id >> 3, c = (id & 7) * 4;
            int so = r * AS + c;
            cpa8(base + so,        Ahg + aoff[i] + k0 + c, av[i]);
            cpa8(base + S_AL + so, Alg + aoff[i] + k0 + c, av[i]);
        }
        #pragma unroll
        for (int i = 0; i < 4; i++) {
            int id = tid + i * 256;
            int kk = id >> 5, n = (id & 31) * 4;
            int so = kk * BS + n;
            size_t go = (size_t)(k0 + kk) * N + n;
            cpa8(base + S_B0H + so, B0hp + go, true);
            cpa8(base + S_B0L + so, B0lp + go, true);
            cpa8(base + S_B1H + so, B1hp + go, true);
            cpa8(base + S_B1L + so, B1lp + go, true);
        }
        asm volatile("cp.async.commit_group;\n" ::);
    };

    issue(0, 0);
    int nk = K / BK;
    for (int kt = 0; kt < nk; kt++) {
        int s = kt & 1;
        asm volatile("cp.async.wait_group 0;\n" ::: "memory");
        __syncthreads();
        if (kt + 1 < nk) issue((kt + 1) * BK, s ^ 1);

        __nv_bfloat16* base = sm + s * STAGE;
        #pragma unroll
        for (int ks = 0; ks < 2; ks++) {
            int kk = ks * 16;
            uint32_t ah[4][4], al[4][4];
            #pragma unroll
            for (int mt = 0; mt < 4; mt++) {
                int row = wm + mt * 16 + (lane & 15);
                int col = kk + ((lane >> 4) << 3);
                ldm4(ah[mt], base + row * AS + col);
                ldm4(al[mt], base + S_AL + row * AS + col);
            }
            int brow = kk + (lane & 15);
            int bcol = wn + ((lane >> 4) << 3);
            {   // B0 -> acc0
                uint32_t bh[2][4], bl[2][4];
                #pragma unroll
                for (int np = 0; np < 2; np++) {
                    ldm4t(bh[np], base + S_B0H + brow * BS + bcol + np * 16);
                    ldm4t(bl[np], base + S_B0L + brow * BS + bcol + np * 16);
                }
                #pragma unroll
                for (int mt = 0; mt < 4; mt++)
                    #pragma unroll
                    for (int nt = 0; nt < 4; nt++) {
                        const uint32_t* bhp = &bh[nt >> 1][(nt & 1) * 2];
                        const uint32_t* blp = &bl[nt >> 1][(nt & 1) * 2];
                        mma16816(acc0[mt][nt], ah[mt], bhp);
                        mma16816(acc0[mt][nt], ah[mt], blp);
                        mma16816(acc0[mt][nt], al[mt], bhp);
                    }
            }
            {   // B1 -> acc1
                uint32_t bh[2][4], bl[2][4];
                #pragma unroll
                for (int np = 0; np < 2; np++) {
                    ldm4t(bh[np], base + S_B1H + brow * BS + bcol + np * 16);
                    ldm4t(bl[np], base + S_B1L + brow * BS + bcol + np * 16);
                }
                #pragma unroll
                for (int mt = 0; mt < 4; mt++)
                    #pragma unroll
                    for (int nt = 0; nt < 4; nt++) {
                        const uint32_t* bhp = &bh[nt >> 1][(nt & 1) * 2];
                        const uint32_t* blp = &bl[nt >> 1][(nt & 1) * 2];
                        mma16816(acc1[mt][nt], ah[mt], bhp);
                        mma16816(acc1[mt][nt], ah[mt], blp);
                        mma16816(acc1[mt][nt], al[mt], bhp);
                    }
            }
        }
        __syncthreads();
    }

    // ---- epilogue ----
    #pragma unroll
    for (int mt = 0; mt < 4; mt++) {
        #pragma unroll
        for (int nt = 0; nt < 4; nt++) {
            int r = m0 + wm + mt * 16 + (lane >> 2);
            int c = col0 + wn + nt * 8 + (lane & 3) * 2;
            if (FUSE) {
                #pragma unroll
                for (int half = 0; half < 2; half++) {
                    int rr = r + half * 8;
                    if (rr < Me) {
                        float g0 = acc0[mt][nt][half * 2 + 0], u0 = acc1[mt][nt][half * 2 + 0];
                        float g1 = acc0[mt][nt][half * 2 + 1], u1 = acc1[mt][nt][half * 2 + 1];
                        float h0 = (g0 / (1.f + __expf(-g0))) * u0;
                        float h1 = (g1 / (1.f + __expf(-g1))) * u1;
                        __nv_bfloat16 hh0, hl0, hh1, hl1;
                        split2(h0, hh0, hl0);
                        split2(h1, hh1, hl1);
                        __nv_bfloat162 H, L;
                        H.x = hh0; H.y = hh1; L.x = hl0; L.y = hl1;
                        size_t o = (size_t)(offe + rr) * II + c;
                        *(__nv_bfloat162*)&g_hh[o] = H;
                        *(__nv_bfloat162*)&g_hl[o] = L;
                    }
                }
            } else {
                if (r < Me) {
                    float2 v0; v0.x = acc0[mt][nt][0]; v0.y = acc0[mt][nt][1];
                    *(float2*)&C[(size_t)(offe + r) * N + c] = v0;
                    float2 v1; v1.x = acc1[mt][nt][0]; v1.y = acc1[mt][nt][1];
                    *(float2*)&C[(size_t)(offe + r) * N + c + BN] = v1;
                }
                if (r + 8 < Me) {
                    float2 v0; v0.x = acc0[mt][nt][2]; v0.y = acc0[mt][nt][3];
                    *(float2*)&C[(size_t)(offe + r + 8) * N + c] = v0;
                    float2 v1; v1.x = acc1[mt][nt][2]; v1.y = acc1[mt][nt][3];
                    *(float2*)&C[(size_t)(offe + r + 8) * N + c + BN] = v1;
                }
            }
        }
    }
}

__global__ void combine_kernel(float* __restrict__ out) {
    int t = blockIdx.x;
    int v0 = g_asg[t * 2 + 0], v1 = g_asg[t * 2 + 1];
    float w0 = g_wt[t * 2 + 0], w1 = g_wt[t * 2 + 1];
    int r0 = g_off[v0 >> 12] + (v0 & 4095);
    int r1 = g_off[v1 >> 12] + (v1 & 4095);
    const float4* y0 = (const float4*)(g_y + (size_t)r0 * HH);
    const float4* y1 = (const float4*)(g_y + (size_t)r1 * HH);
    float4* o = (float4*)(out + (size_t)t * HH);
    for (int i = threadIdx.x; i < HH / 4; i += blockDim.x) {
        float4 a = y0[i], b = y1[i], r;
        r.x = w0 * a.x + w1 * b.x;
        r.y = w0 * a.y + w1 * b.y;
        r.z = w0 * a.z + w1 * b.z;
        r.w = w0 * a.w + w1 * b.w;
        o[i] = r;
    }
}

// ---------------- launch ------------------------------------------------------
extern "C" void kernel_launch(void* const* d_in, const int* in_sizes, int n_in,
                              void* d_out, int out_size)
{
    (void)in_sizes; (void)n_in; (void)out_size;
    const float* x  = (const float*)d_in[0];
    const float* gw = (const float*)d_in[1];
    const float* wg = (const float*)d_in[2];
    const float* wu = (const float*)d_in[3];
    const float* wd = (const float*)d_in[4];
    float* out = (float*)d_out;

    void *xh, *xl, *wgh, *wgl, *wuh, *wul, *wdh, *wdl, *hh, *hl, *y;
    cudaGetSymbolAddress(&xh, g_xh);   cudaGetSymbolAddress(&xl, g_xl);
    cudaGetSymbolAddress(&wgh, g_wgh); cudaGetSymbolAddress(&wgl, g_wgl);
    cudaGetSymbolAddress(&wuh, g_wuh); cudaGetSymbolAddress(&wul, g_wul);
    cudaGetSymbolAddress(&wdh, g_wdh); cudaGetSymbolAddress(&wdl, g_wdl);
    cudaGetSymbolAddress(&hh, g_hh);   cudaGetSymbolAddress(&hl, g_hl);
    cudaGetSymbolAddress(&y, g_y);

    cudaFuncSetAttribute(gemm3<true, true>,   cudaFuncAttributeMaxDynamicSharedMemorySize, SMEMB);
    cudaFuncSetAttribute(gemm3<false, false>, cudaFuncAttributeMaxDynamicSharedMemorySize, SMEMB);

    zero_cnt_kernel<<<1, 32>>>();
    router_kernel<<<TT, 256>>>(x, gw);
    prefix_kernel<<<1, 1>>>();

    // pre-split operands into bf16 hi/lo planes (row-major, no transpose)
    int wblk = (EE * HH * (II / 4)) / 256;      // 65536
    split_kernel<<<wblk, 256>>>((const float4*)wg, (uint2*)wgh, (uint2*)wgl);
    split_kernel<<<wblk, 256>>>((const float4*)wu, (uint2*)wuh, (uint2*)wul);
    split_kernel<<<wblk, 256>>>((const float4*)wd, (uint2*)wdh, (uint2*)wdl);
    split_kernel<<<(TT * (HH / 4)) / 256, 256>>>((const float4*)x, (uint2*)xh, (uint2*)xl);

    // gate+up fused GEMM with swiglu epilogue -> hh/hl
    dim3 g1(II / BN, TT / BM, EE);              // (32, 32, 8)
    gemm3<true, true><<<g1, 256, SMEMB>>>(
        (const __nv_bfloat16*)xh, (const __nv_bfloat16*)xl,
        (const __nv_bfloat16*)wgh, (const __nv_bfloat16*)wgl,
        (const __nv_bfloat16*)wuh, (const __nv_bfloat16*)wul,
        nullptr, HH, II);

    // down GEMM: two adjacent 128-col tiles per CTA -> y
    dim3 g2(HH / (2 * BN), TT / BM, EE);        // (8, 32, 8)
    gemm3<false, false><<<g2, 256, SMEMB>>>(
        (const __nv_bfloat16*)hh, (const __nv_bfloat16*)hl,
        (const __nv_bfloat16*)wdh, (const __nv_bfloat16*)wdl,
        (const __nv_bfloat16*)wdh, (const __nv_bfloat16*)wdl,
        (float*)y, II, HH);

    combine_kernel<<<TT, 256>>>(out);
}